// round 5
// baseline (speedup 1.0000x reference)
#include <cuda_runtime.h>
#include <math.h>

#define N_NODES 100000
#define N_EDGES 3200000
#define D_IN    128
#define D_HID   16
#define D_OUT   2

#define SCAN_BS 1024
#define NBLK    ((N_NODES + SCAN_BS - 1) / SCAN_BS)   // 98

// ---- scratch (static __device__ globals; no allocations) ----
__device__ int   g_src[N_EDGES];
__device__ int   g_dst[N_EDGES];
__device__ int   g_csr[N_EDGES];           // src ids grouped by dst
__device__ int   g_deg[N_NODES];
__device__ int   g_scantmp[N_NODES];
__device__ int   g_rowptr[N_NODES + 1];
__device__ int   g_cursor[N_NODES];
__device__ int   g_bsum[NBLK];
__device__ float g_dinv[N_NODES];
__device__ float g_h1 [N_NODES * D_HID];   // x @ W1 (pre-aggregation)
__device__ float g_h2 [N_NODES * D_OUT];   // layer-2 pre-aggregation features
__device__ int   g_is64;                   // edge_index element width flag

// ---------------------------------------------------------------------------
// Detect whether edge_index buffer is int64 or int32.
// Values are < 2^17, so an int64 buffer viewed as int32 words is [v,0,v,0,...]:
// all odd words zero. A genuine int32 buffer has nonzero odd words (w.h.p.).
__global__ void k_detect(const int* __restrict__ ei32) {
    if (threadIdx.x == 0) {
        int z = 0;
        for (int k = 0; k < 16; k++) z |= ei32[2 * k + 1];
        g_is64 = (z == 0) ? 1 : 0;
    }
}

__global__ void k_zero_deg() {
    int i = blockIdx.x * blockDim.x + threadIdx.x;
    if (i < N_NODES) g_deg[i] = 0;
}

// edge_index -> int32 src/dst + in-degree count. 2 edges per thread.
__global__ void k_convert(const void* __restrict__ eiv) {
    int e = (blockIdx.x * blockDim.x + threadIdx.x) * 2;
    if (e >= N_EDGES) return;
    int s0, s1, d0, d1;
    if (g_is64) {
        const long long* ei = (const long long*)eiv;
        longlong2 sv = *(const longlong2*)(ei + e);
        longlong2 dv = *(const longlong2*)(ei + N_EDGES + e);
        s0 = (int)sv.x; s1 = (int)sv.y;
        d0 = (int)dv.x; d1 = (int)dv.y;
    } else {
        const int* ei = (const int*)eiv;
        int2 sv = *(const int2*)(ei + e);
        int2 dv = *(const int2*)(ei + N_EDGES + e);
        s0 = sv.x; s1 = sv.y;
        d0 = dv.x; d1 = dv.y;
    }
    g_src[e]     = s0;  g_src[e + 1] = s1;
    g_dst[e]     = d0;  g_dst[e + 1] = d1;
    atomicAdd(&g_deg[d0], 1);
    atomicAdd(&g_deg[d1], 1);
}

// block-local inclusive scan of deg
__global__ void k_scan1() {
    __shared__ int sm[SCAN_BS];
    int t = threadIdx.x;
    int i = blockIdx.x * SCAN_BS + t;
    int v = (i < N_NODES) ? g_deg[i] : 0;
    sm[t] = v;
    __syncthreads();
    for (int off = 1; off < SCAN_BS; off <<= 1) {
        int add = (t >= off) ? sm[t - off] : 0;
        __syncthreads();
        sm[t] += add;
        __syncthreads();
    }
    if (i < N_NODES) g_scantmp[i] = sm[t];
    if (t == SCAN_BS - 1) g_bsum[blockIdx.x] = sm[t];
}

// exclusive scan of the 98 block sums (tiny, serial)
__global__ void k_scan2() {
    if (threadIdx.x == 0) {
        int acc = 0;
        for (int b = 0; b < NBLK; b++) { int v = g_bsum[b]; g_bsum[b] = acc; acc += v; }
        g_rowptr[N_NODES] = acc;   // == N_EDGES
    }
}

// finalize rowptr (exclusive), cursors, dinv = rsqrt(indeg + 1)
__global__ void k_scan3() {
    int i = blockIdx.x * blockDim.x + threadIdx.x;
    if (i < N_NODES) {
        int deg  = g_deg[i];
        int excl = g_scantmp[i] - deg + g_bsum[i >> 10];
        g_rowptr[i] = excl;
        g_cursor[i] = excl;
        g_dinv[i]   = rsqrtf((float)(deg + 1));
    }
}

// scatter src ids into dst buckets
__global__ void k_fillcsr() {
    int e = blockIdx.x * blockDim.x + threadIdx.x;
    if (e < N_EDGES) {
        int d   = g_dst[e];
        int pos = atomicAdd(&g_cursor[d], 1);
        g_csr[pos] = g_src[e];
    }
}

// ---------------------------------------------------------------------------
// h1 = x @ W1  (100000x128 @ 128x16). Block handles 16 nodes; x rows + W1 in smem.
__global__ void k_gemm1(const float* __restrict__ x, const float* __restrict__ W1) {
    __shared__ float W1s[D_IN * D_HID];   // [k][j]
    __shared__ float xs[16][D_IN];
    int t  = threadIdx.x;                 // 256 threads
    int n0 = blockIdx.x * 16;

    for (int idx = t; idx < D_IN * D_HID; idx += 256) W1s[idx] = W1[idx];
    {   // vectorized row load: 16 rows x 128 floats = 512 float4
        const float4* x4 = (const float4*)x;
        for (int idx = t; idx < 16 * (D_IN / 4); idx += 256) {
            int ln = idx >> 5, q = idx & 31;     // 32 float4 per row
            int n  = n0 + ln;
            float4 v = (n < N_NODES) ? x4[n * (D_IN / 4) + q]
                                     : make_float4(0.f, 0.f, 0.f, 0.f);
            *(float4*)&xs[ln][q * 4] = v;
        }
    }
    __syncthreads();

    int j = t & 15, ln = t >> 4;
    int n = n0 + ln;
    if (n < N_NODES) {
        float acc = 0.f;
#pragma unroll
        for (int k = 0; k < D_IN; k++)
            acc += xs[ln][k] * W1s[k * D_HID + j];
        g_h1[n * D_HID + j] = acc;
    }
}

// Layer-1 aggregation + bias + relu + FUSED 16->2 projection (layer-2 gemm).
// Half-warp per node, lane j = hidden feature. Prefetched gather loop.
__global__ void k_agg1(const float* __restrict__ b1, const float* __restrict__ W2) {
    int t = blockIdx.x * blockDim.x + threadIdx.x;
    int n = t >> 4;
    int j = t & 15;
    if (n >= N_NODES) return;

    float dn  = g_dinv[n];
    float acc = g_h1[n * D_HID + j] * dn;      // self loop (x dn again below)
    int p  = g_rowptr[n];
    int pe = g_rowptr[n + 1];

    if (p < pe) {
        int s = g_csr[p];                       // prefetch first index
        for (++p; p < pe; ++p) {
            int s_next = g_csr[p];              // overlap next index load
            acc += g_h1[s * D_HID + j] * g_dinv[s];
            s = s_next;
        }
        acc += g_h1[s * D_HID + j] * g_dinv[s];
    }

    float v = fmaxf(acc * dn + b1[j], 0.f);

    // fused projection: reduce v*W2 across the 16 lanes of this node
    float z0 = v * W2[j * 2 + 0];
    float z1 = v * W2[j * 2 + 1];
#pragma unroll
    for (int o = 8; o; o >>= 1) {
        z0 += __shfl_xor_sync(0xFFFFFFFFu, z0, o, 16);
        z1 += __shfl_xor_sync(0xFFFFFFFFu, z1, o, 16);
    }
    if (j == 0) {
        g_h2[n * 2 + 0] = z0;
        g_h2[n * 2 + 1] = z1;
    }
}

// layer-2 aggregation + log_softmax: warp per node, lanes stride edge list
__global__ void k_agg2(const float* __restrict__ b2, float* __restrict__ out) {
    int warp = (blockIdx.x * blockDim.x + threadIdx.x) >> 5;
    int lane = threadIdx.x & 31;
    if (warp >= N_NODES) return;
    int n  = warp;
    int p0 = g_rowptr[n];
    int p1 = g_rowptr[n + 1];

    float z0 = 0.f, z1 = 0.f;
    for (int p = p0 + lane; p < p1; p += 32) {
        int s  = g_csr[p];
        float w = g_dinv[s];
        z0 += g_h2[s * 2 + 0] * w;
        z1 += g_h2[s * 2 + 1] * w;
    }
#pragma unroll
    for (int o = 16; o; o >>= 1) {
        z0 += __shfl_xor_sync(0xFFFFFFFFu, z0, o);
        z1 += __shfl_xor_sync(0xFFFFFFFFu, z1, o);
    }
    if (lane == 0) {
        float dn = g_dinv[n];
        z0 = dn * (z0 + g_h2[n * 2 + 0] * dn) + b2[0];
        z1 = dn * (z1 + g_h2[n * 2 + 1] * dn) + b2[1];
        float m = fmaxf(z0, z1);
        float l = m + logf(expf(z0 - m) + expf(z1 - m));
        out[n * 2 + 0] = z0 - l;
        out[n * 2 + 1] = z1 - l;
    }
}

// ---------------------------------------------------------------------------
extern "C" void kernel_launch(void* const* d_in, const int* in_sizes, int n_in,
                              void* d_out, int out_size) {
    // Identify inputs by element count (all six are distinct) — immune to
    // metadata ordering.
    const float* x  = 0; const float* W1 = 0; const float* b1 = 0;
    const float* W2 = 0; const float* b2 = 0; const void*  ei = 0;
    for (int i = 0; i < n_in; i++) {
        switch (in_sizes[i]) {
            case N_NODES * D_IN: x  = (const float*)d_in[i]; break;  // 12,800,000
            case D_IN * D_HID:   W1 = (const float*)d_in[i]; break;  // 2048
            case D_HID:          b1 = (const float*)d_in[i]; break;  // 16
            case D_HID * D_OUT:  W2 = (const float*)d_in[i]; break;  // 32
            case D_OUT:          b2 = (const float*)d_in[i]; break;  // 2
            case 2 * N_EDGES:    ei = d_in[i];               break;  // 6,400,000
        }
    }
    float* out = (float*)d_out;

    k_detect  <<<1, 32>>>((const int*)ei);
    k_zero_deg<<<(N_NODES + 255) / 256, 256>>>();
    k_convert <<<(N_EDGES / 2 + 255) / 256, 256>>>(ei);
    k_scan1   <<<NBLK, SCAN_BS>>>();
    k_scan2   <<<1, 32>>>();
    k_scan3   <<<(N_NODES + 255) / 256, 256>>>();
    k_fillcsr <<<(N_EDGES + 255) / 256, 256>>>();
    k_gemm1   <<<(N_NODES + 15) / 16, 256>>>(x, W1);
    k_agg1    <<<(N_NODES * 16 + 255) / 256, 256>>>(b1, W2);
    k_agg2    <<<(N_NODES * 32 + 255) / 256, 256>>>(b2, out);
}

// round 6
// speedup vs baseline: 1.0454x; 1.0454x over previous
#include <cuda_runtime.h>
#include <math.h>

#define N_NODES 100000
#define N_EDGES 3200000
#define D_IN    128
#define D_HID   16
#define D_OUT   2

// ---- scratch (static __device__ globals; no allocations) ----
__device__ int   g_src[N_EDGES];
__device__ int   g_dst[N_EDGES];
__device__ int   g_csr[N_EDGES];           // src ids grouped by dst (bucketed)
__device__ int   g_deg[N_NODES];
__device__ int   g_rowptr[N_NODES];        // bucket start per node (non-monotone)
__device__ int   g_cursor[N_NODES];
__device__ float g_dinv[N_NODES];
__device__ float g_h1 [N_NODES * D_HID];   // x @ W1 (pre-aggregation)
__device__ float g_h2 [N_NODES * D_OUT];   // layer-2 pre-aggregation features
__device__ int   g_is64;                   // edge_index element width flag
__device__ int   g_total;                  // CSR allocation counter

// ---------------------------------------------------------------------------
// Zero degrees + allocation counter; thread 0 detects edge_index width.
// int64 values < 2^17 viewed as int32 words are [v,0,v,0,...]: odd words zero.
__global__ void k_init(const int* __restrict__ ei32) {
    int i = blockIdx.x * blockDim.x + threadIdx.x;
    if (i < N_NODES) g_deg[i] = 0;
    if (i == 0) {
        g_total = 0;
        int z = 0;
#pragma unroll
        for (int k = 0; k < 16; k++) z |= ei32[2 * k + 1];
        g_is64 = (z == 0) ? 1 : 0;
    }
}

// edge_index -> int32 src/dst + in-degree count. 2 edges per thread.
__global__ void k_convert(const void* __restrict__ eiv) {
    int e = (blockIdx.x * blockDim.x + threadIdx.x) * 2;
    if (e >= N_EDGES) return;
    int s0, s1, d0, d1;
    if (g_is64) {
        const long long* ei = (const long long*)eiv;
        longlong2 sv = *(const longlong2*)(ei + e);
        longlong2 dv = *(const longlong2*)(ei + N_EDGES + e);
        s0 = (int)sv.x; s1 = (int)sv.y;
        d0 = (int)dv.x; d1 = (int)dv.y;
    } else {
        const int* ei = (const int*)eiv;
        int2 sv = *(const int2*)(ei + e);
        int2 dv = *(const int2*)(ei + N_EDGES + e);
        s0 = sv.x; s1 = sv.y;
        d0 = dv.x; d1 = dv.y;
    }
    g_src[e]     = s0;  g_src[e + 1] = s1;
    g_dst[e]     = d0;  g_dst[e + 1] = d1;
    atomicAdd(&g_deg[d0], 1);
    atomicAdd(&g_deg[d1], 1);
}

// Allocate CSR buckets: warp shfl-scan of degrees + one atomicAdd per warp.
// rowptr[n] = bucket start (not monotone across nodes; end = start + deg).
// Also computes dinv = rsqrt(deg+1) and initializes cursors.
__global__ void k_offsets() {
    int i    = blockIdx.x * blockDim.x + threadIdx.x;
    int lane = threadIdx.x & 31;
    int deg  = (i < N_NODES) ? g_deg[i] : 0;

    int incl = deg;
#pragma unroll
    for (int o = 1; o < 32; o <<= 1) {
        int v = __shfl_up_sync(0xFFFFFFFFu, incl, o);
        if (lane >= o) incl += v;
    }
    int base = 0;
    if (lane == 31) base = atomicAdd(&g_total, incl);   // incl = warp total
    base = __shfl_sync(0xFFFFFFFFu, base, 31);

    if (i < N_NODES) {
        int off = base + incl - deg;
        g_rowptr[i] = off;
        g_cursor[i] = off;
        g_dinv[i]   = rsqrtf((float)(deg + 1));
    }
}

// scatter src ids into dst buckets
__global__ void k_fillcsr() {
    int e = blockIdx.x * blockDim.x + threadIdx.x;
    if (e < N_EDGES) {
        int d   = g_dst[e];
        int pos = atomicAdd(&g_cursor[d], 1);
        g_csr[pos] = g_src[e];
    }
}

// ---------------------------------------------------------------------------
// h1 = x @ W1  (100000x128 @ 128x16). Block handles 16 nodes; x rows + W1 in smem.
__global__ void k_gemm1(const float* __restrict__ x, const float* __restrict__ W1) {
    __shared__ float W1s[D_IN * D_HID];   // [k][j]
    __shared__ float xs[16][D_IN];
    int t  = threadIdx.x;                 // 256 threads
    int n0 = blockIdx.x * 16;

    for (int idx = t; idx < D_IN * D_HID; idx += 256) W1s[idx] = W1[idx];
    {   // vectorized row load: 16 rows x 128 floats = 512 float4
        const float4* x4 = (const float4*)x;
        for (int idx = t; idx < 16 * (D_IN / 4); idx += 256) {
            int ln = idx >> 5, q = idx & 31;     // 32 float4 per row
            int n  = n0 + ln;
            float4 v = (n < N_NODES) ? x4[n * (D_IN / 4) + q]
                                     : make_float4(0.f, 0.f, 0.f, 0.f);
            *(float4*)&xs[ln][q * 4] = v;
        }
    }
    __syncthreads();

    int j = t & 15, ln = t >> 4;
    int n = n0 + ln;
    if (n < N_NODES) {
        float acc = 0.f;
#pragma unroll
        for (int k = 0; k < D_IN; k++)
            acc += xs[ln][k] * W1s[k * D_HID + j];
        g_h1[n * D_HID + j] = acc;
    }
}

// Layer-1 aggregation + bias + relu + FUSED 16->2 projection.
// Half-warp per node, lane j = hidden feature. 4x-unrolled gather (MLP~8).
__global__ void k_agg1(const float* __restrict__ b1, const float* __restrict__ W2) {
    int t = blockIdx.x * blockDim.x + threadIdx.x;
    int n = t >> 4;
    int j = t & 15;
    if (n >= N_NODES) return;

    float dn  = g_dinv[n];
    float acc = g_h1[n * D_HID + j] * dn;      // self loop (x dn again below)
    int p  = g_rowptr[n];
    int pe = p + g_deg[n];

    for (; p + 4 <= pe; p += 4) {
        int sa = g_csr[p + 0], sb = g_csr[p + 1];
        int sc = g_csr[p + 2], sd = g_csr[p + 3];
        float ha = g_h1[sa * D_HID + j], hb = g_h1[sb * D_HID + j];
        float hc = g_h1[sc * D_HID + j], hd = g_h1[sd * D_HID + j];
        float da = g_dinv[sa], db = g_dinv[sb];
        float dc = g_dinv[sc], dd = g_dinv[sd];
        acc += ha * da + hb * db + hc * dc + hd * dd;
    }
    for (; p < pe; ++p) {
        int s = g_csr[p];
        acc += g_h1[s * D_HID + j] * g_dinv[s];
    }

    float v = fmaxf(acc * dn + b1[j], 0.f);

    // fused projection: reduce v*W2 across the 16 lanes of this node
    float z0 = v * W2[j * 2 + 0];
    float z1 = v * W2[j * 2 + 1];
#pragma unroll
    for (int o = 8; o; o >>= 1) {
        z0 += __shfl_xor_sync(0xFFFFFFFFu, z0, o, 16);
        z1 += __shfl_xor_sync(0xFFFFFFFFu, z1, o, 16);
    }
    if (j == 0) {
        g_h2[n * 2 + 0] = z0;
        g_h2[n * 2 + 1] = z1;
    }
}

// layer-2 aggregation + log_softmax: warp per node, lanes stride edge list
__global__ void k_agg2(const float* __restrict__ b2, float* __restrict__ out) {
    int warp = (blockIdx.x * blockDim.x + threadIdx.x) >> 5;
    int lane = threadIdx.x & 31;
    if (warp >= N_NODES) return;
    int n  = warp;
    int p0 = g_rowptr[n];
    int p1 = p0 + g_deg[n];

    const float2* h2v = (const float2*)g_h2;
    float z0 = 0.f, z1 = 0.f;
    for (int p = p0 + lane; p < p1; p += 32) {
        int s   = g_csr[p];
        float w = g_dinv[s];
        float2 h = h2v[s];
        z0 += h.x * w;
        z1 += h.y * w;
    }
#pragma unroll
    for (int o = 16; o; o >>= 1) {
        z0 += __shfl_xor_sync(0xFFFFFFFFu, z0, o);
        z1 += __shfl_xor_sync(0xFFFFFFFFu, z1, o);
    }
    if (lane == 0) {
        float dn = g_dinv[n];
        float2 hn = h2v[n];
        z0 = dn * (z0 + hn.x * dn) + b2[0];
        z1 = dn * (z1 + hn.y * dn) + b2[1];
        float m = fmaxf(z0, z1);
        float l = m + logf(expf(z0 - m) + expf(z1 - m));
        float2 r; r.x = z0 - l; r.y = z1 - l;
        *(float2*)(out + n * 2) = r;
    }
}

// ---------------------------------------------------------------------------
extern "C" void kernel_launch(void* const* d_in, const int* in_sizes, int n_in,
                              void* d_out, int out_size) {
    // Identify inputs by element count (all six are distinct).
    const float* x  = 0; const float* W1 = 0; const float* b1 = 0;
    const float* W2 = 0; const float* b2 = 0; const void*  ei = 0;
    for (int i = 0; i < n_in; i++) {
        switch (in_sizes[i]) {
            case N_NODES * D_IN: x  = (const float*)d_in[i]; break;  // 12,800,000
            case D_IN * D_HID:   W1 = (const float*)d_in[i]; break;  // 2048
            case D_HID:          b1 = (const float*)d_in[i]; break;  // 16
            case D_HID * D_OUT:  W2 = (const float*)d_in[i]; break;  // 32
            case D_OUT:          b2 = (const float*)d_in[i]; break;  // 2
            case 2 * N_EDGES:    ei = d_in[i];               break;  // 6,400,000
        }
    }
    float* out = (float*)d_out;

    k_init    <<<(N_NODES + 255) / 256, 256>>>((const int*)ei);
    k_convert <<<(N_EDGES / 2 + 255) / 256, 256>>>(ei);
    k_offsets <<<(N_NODES + 255) / 256, 256>>>();
    k_fillcsr <<<(N_EDGES + 255) / 256, 256>>>();
    k_gemm1   <<<(N_NODES + 15) / 16, 256>>>(x, W1);
    k_agg1    <<<(N_NODES * 16 + 255) / 256, 256>>>(b1, W2);
    k_agg2    <<<(N_NODES * 32 + 255) / 256, 256>>>(b2, out);
}

// round 7
// speedup vs baseline: 1.0799x; 1.0330x over previous
#include <cuda_runtime.h>
#include <math.h>

#define N_NODES 100000
#define N_EDGES 3200000
#define D_IN    128
#define D_HID   16
#define D_OUT   2

// ---- scratch (static __device__ globals; no allocations) ----
__device__ int   g_csr[N_EDGES];           // src ids grouped by dst (bucketed)
__device__ int   g_deg[N_NODES];
__device__ int   g_rowptr[N_NODES];        // bucket start per node (non-monotone)
__device__ int   g_cursor[N_NODES];
__device__ float g_dinv[N_NODES];
__device__ float g_h1 [N_NODES * D_HID];   // x @ W1 (pre-aggregation)
__device__ float g_h2 [N_NODES * D_OUT];   // layer-2 pre-aggregation features
__device__ int   g_is64;                   // edge_index element width flag
__device__ int   g_total;                  // CSR allocation counter

// ---------------------------------------------------------------------------
// Zero degrees + allocation counter; thread 0 detects edge_index width.
// int64 values < 2^17 viewed as int32 words are [v,0,v,0,...]: odd words zero.
__global__ void k_init(const int* __restrict__ ei32) {
    int i = blockIdx.x * blockDim.x + threadIdx.x;
    if (i < N_NODES) g_deg[i] = 0;
    if (i == 0) {
        g_total = 0;
        int z = 0;
#pragma unroll
        for (int k = 0; k < 16; k++) z |= ei32[2 * k + 1];
        g_is64 = (z == 0) ? 1 : 0;
    }
}

// In-degree count from the dst half of edge_index. 8 edges/thread (8 indep atomics).
__global__ void k_degree(const void* __restrict__ eiv) {
    int e = (blockIdx.x * blockDim.x + threadIdx.x) * 8;
    if (e >= N_EDGES) return;
    int d[8];
    if (g_is64) {
        const longlong2* p = (const longlong2*)((const long long*)eiv + N_EDGES + e);
#pragma unroll
        for (int q = 0; q < 4; q++) {
            longlong2 v = p[q];
            d[2*q]   = (int)v.x;
            d[2*q+1] = (int)v.y;
        }
    } else {
        const int4* p = (const int4*)((const int*)eiv + N_EDGES + e);
#pragma unroll
        for (int q = 0; q < 2; q++) {
            int4 v = p[q];
            d[4*q] = v.x; d[4*q+1] = v.y; d[4*q+2] = v.z; d[4*q+3] = v.w;
        }
    }
#pragma unroll
    for (int q = 0; q < 8; q++) atomicAdd(&g_deg[d[q]], 1);
}

// Allocate CSR buckets: warp shfl-scan of degrees + one atomicAdd per warp.
// rowptr[n] = bucket start (not monotone across nodes; end = start + deg).
__global__ void k_offsets() {
    int i    = blockIdx.x * blockDim.x + threadIdx.x;
    int lane = threadIdx.x & 31;
    int deg  = (i < N_NODES) ? g_deg[i] : 0;

    int incl = deg;
#pragma unroll
    for (int o = 1; o < 32; o <<= 1) {
        int v = __shfl_up_sync(0xFFFFFFFFu, incl, o);
        if (lane >= o) incl += v;
    }
    int base = 0;
    if (lane == 31) base = atomicAdd(&g_total, incl);   // incl = warp total
    base = __shfl_sync(0xFFFFFFFFu, base, 31);

    if (i < N_NODES) {
        int off = base + incl - deg;
        g_rowptr[i] = off;
        g_cursor[i] = off;
        g_dinv[i]   = rsqrtf((float)(deg + 1));
    }
}

// Scatter src ids into dst buckets. 8 edges/thread, reads edge_index directly
// (L2-resident after k_degree). 8 independent atomic->store chains.
__global__ void k_fillcsr(const void* __restrict__ eiv) {
    int e = (blockIdx.x * blockDim.x + threadIdx.x) * 8;
    if (e >= N_EDGES) return;
    int s[8], d[8];
    if (g_is64) {
        const longlong2* ps = (const longlong2*)((const long long*)eiv + e);
        const longlong2* pd = (const longlong2*)((const long long*)eiv + N_EDGES + e);
#pragma unroll
        for (int q = 0; q < 4; q++) {
            longlong2 sv = ps[q], dv = pd[q];
            s[2*q]   = (int)sv.x;  s[2*q+1] = (int)sv.y;
            d[2*q]   = (int)dv.x;  d[2*q+1] = (int)dv.y;
        }
    } else {
        const int4* ps = (const int4*)((const int*)eiv + e);
        const int4* pd = (const int4*)((const int*)eiv + N_EDGES + e);
#pragma unroll
        for (int q = 0; q < 2; q++) {
            int4 sv = ps[q], dv = pd[q];
            s[4*q] = sv.x; s[4*q+1] = sv.y; s[4*q+2] = sv.z; s[4*q+3] = sv.w;
            d[4*q] = dv.x; d[4*q+1] = dv.y; d[4*q+2] = dv.z; d[4*q+3] = dv.w;
        }
    }
    int pos[8];
#pragma unroll
    for (int q = 0; q < 8; q++) pos[q] = atomicAdd(&g_cursor[d[q]], 1);
#pragma unroll
    for (int q = 0; q < 8; q++) g_csr[pos[q]] = s[q];
}

// ---------------------------------------------------------------------------
// h1 = x @ W1  (100000x128 @ 128x16). Block handles 16 nodes; x rows + W1 in smem.
__global__ void k_gemm1(const float* __restrict__ x, const float* __restrict__ W1) {
    __shared__ float W1s[D_IN * D_HID];   // [k][j]
    __shared__ float xs[16][D_IN];
    int t  = threadIdx.x;                 // 256 threads
    int n0 = blockIdx.x * 16;

    for (int idx = t; idx < D_IN * D_HID; idx += 256) W1s[idx] = W1[idx];
    {   // vectorized row load: 16 rows x 128 floats = 512 float4
        const float4* x4 = (const float4*)x;
        for (int idx = t; idx < 16 * (D_IN / 4); idx += 256) {
            int ln = idx >> 5, q = idx & 31;     // 32 float4 per row
            int n  = n0 + ln;
            float4 v = (n < N_NODES) ? x4[n * (D_IN / 4) + q]
                                     : make_float4(0.f, 0.f, 0.f, 0.f);
            *(float4*)&xs[ln][q * 4] = v;
        }
    }
    __syncthreads();

    int j = t & 15, ln = t >> 4;
    int n = n0 + ln;
    if (n < N_NODES) {
        float acc = 0.f;
#pragma unroll
        for (int k = 0; k < D_IN; k++)
            acc += xs[ln][k] * W1s[k * D_HID + j];
        g_h1[n * D_HID + j] = acc;
    }
}

// Layer-1 aggregation + bias + relu + FUSED 16->2 projection.
// Half-warp per node, lane j = hidden feature. 4x-unrolled gather (MLP~8).
__global__ void k_agg1(const float* __restrict__ b1, const float* __restrict__ W2) {
    int t = blockIdx.x * blockDim.x + threadIdx.x;
    int n = t >> 4;
    int j = t & 15;
    if (n >= N_NODES) return;

    float dn  = g_dinv[n];
    float acc = g_h1[n * D_HID + j] * dn;      // self loop (x dn again below)
    int p  = g_rowptr[n];
    int pe = p + g_deg[n];

    for (; p + 4 <= pe; p += 4) {
        int sa = g_csr[p + 0], sb = g_csr[p + 1];
        int sc = g_csr[p + 2], sd = g_csr[p + 3];
        float ha = g_h1[sa * D_HID + j], hb = g_h1[sb * D_HID + j];
        float hc = g_h1[sc * D_HID + j], hd = g_h1[sd * D_HID + j];
        float da = g_dinv[sa], db = g_dinv[sb];
        float dc = g_dinv[sc], dd = g_dinv[sd];
        acc += ha * da + hb * db + hc * dc + hd * dd;
    }
    for (; p < pe; ++p) {
        int s = g_csr[p];
        acc += g_h1[s * D_HID + j] * g_dinv[s];
    }

    float v = fmaxf(acc * dn + b1[j], 0.f);

    // fused projection: reduce v*W2 across the 16 lanes of this node
    float z0 = v * W2[j * 2 + 0];
    float z1 = v * W2[j * 2 + 1];
#pragma unroll
    for (int o = 8; o; o >>= 1) {
        z0 += __shfl_xor_sync(0xFFFFFFFFu, z0, o, 16);
        z1 += __shfl_xor_sync(0xFFFFFFFFu, z1, o, 16);
    }
    if (j == 0) {
        g_h2[n * 2 + 0] = z0;
        g_h2[n * 2 + 1] = z1;
    }
}

// layer-2 aggregation + log_softmax: warp per node, lanes stride edge list
__global__ void k_agg2(const float* __restrict__ b2, float* __restrict__ out) {
    int warp = (blockIdx.x * blockDim.x + threadIdx.x) >> 5;
    int lane = threadIdx.x & 31;
    if (warp >= N_NODES) return;
    int n  = warp;
    int p0 = g_rowptr[n];
    int p1 = p0 + g_deg[n];

    const float2* h2v = (const float2*)g_h2;
    float z0 = 0.f, z1 = 0.f;
    for (int p = p0 + lane; p < p1; p += 32) {
        int s   = g_csr[p];
        float w = g_dinv[s];
        float2 h = h2v[s];
        z0 += h.x * w;
        z1 += h.y * w;
    }
#pragma unroll
    for (int o = 16; o; o >>= 1) {
        z0 += __shfl_xor_sync(0xFFFFFFFFu, z0, o);
        z1 += __shfl_xor_sync(0xFFFFFFFFu, z1, o);
    }
    if (lane == 0) {
        float dn = g_dinv[n];
        float2 hn = h2v[n];
        z0 = dn * (z0 + hn.x * dn) + b2[0];
        z1 = dn * (z1 + hn.y * dn) + b2[1];
        float m = fmaxf(z0, z1);
        float l = m + logf(expf(z0 - m) + expf(z1 - m));
        float2 r; r.x = z0 - l; r.y = z1 - l;
        *(float2*)(out + n * 2) = r;
    }
}

// ---------------------------------------------------------------------------
extern "C" void kernel_launch(void* const* d_in, const int* in_sizes, int n_in,
                              void* d_out, int out_size) {
    // Identify inputs by element count (all six are distinct).
    const float* x  = 0; const float* W1 = 0; const float* b1 = 0;
    const float* W2 = 0; const float* b2 = 0; const void*  ei = 0;
    for (int i = 0; i < n_in; i++) {
        switch (in_sizes[i]) {
            case N_NODES * D_IN: x  = (const float*)d_in[i]; break;  // 12,800,000
            case D_IN * D_HID:   W1 = (const float*)d_in[i]; break;  // 2048
            case D_HID:          b1 = (const float*)d_in[i]; break;  // 16
            case D_HID * D_OUT:  W2 = (const float*)d_in[i]; break;  // 32
            case D_OUT:          b2 = (const float*)d_in[i]; break;  // 2
            case 2 * N_EDGES:    ei = d_in[i];               break;  // 6,400,000
        }
    }
    float* out = (float*)d_out;

    k_init    <<<(N_NODES + 255) / 256, 256>>>((const int*)ei);
    k_degree  <<<(N_EDGES / 8 + 255) / 256, 256>>>(ei);
    k_offsets <<<(N_NODES + 255) / 256, 256>>>();
    k_fillcsr <<<(N_EDGES / 8 + 255) / 256, 256>>>(ei);
    k_gemm1   <<<(N_NODES + 15) / 16, 256>>>(x, W1);
    k_agg1    <<<(N_NODES * 16 + 255) / 256, 256>>>(b1, W2);
    k_agg2    <<<(N_NODES * 32 + 255) / 256, 256>>>(b2, out);
}

// round 9
// speedup vs baseline: 1.1844x; 1.0968x over previous
#include <cuda_runtime.h>
#include <math.h>

#define N_NODES 100000
#define N_EDGES 3200000
#define D_IN    128
#define D_HID   16
#define D_OUT   2

#define GB_FILL ((N_EDGES / 8 + 255) / 256)   // 1563 blocks, 8 edges/thread
#define GB_GEMM ((N_NODES + 15) / 16)         // 6250 blocks, 16 nodes/block

// ---- scratch (static __device__ globals; no allocations) ----
__device__ int   g_csr[N_EDGES];           // src ids grouped by dst (bucketed)
__device__ int   g_deg[N_NODES];
__device__ int   g_rowptr[N_NODES];        // bucket start per node (non-monotone)
__device__ int   g_cursor[N_NODES];
__device__ float g_dinv[N_NODES];
__device__ float g_h1 [N_NODES * D_HID];   // (x @ W1) * dinv[n]  (pre-scaled)
__device__ float g_h2 [N_NODES * D_OUT];   // layer-2 features * dinv[n] (pre-scaled)
__device__ int   g_is64;                   // edge_index element width flag
__device__ int   g_total;                  // CSR allocation counter

// ---------------------------------------------------------------------------
// Zero degrees + allocation counter; thread 0 detects edge_index width.
// int64 values < 2^17 viewed as int32 words are [v,0,v,0,...]: odd words zero.
__global__ void k_init(const int* __restrict__ ei32) {
    int i = blockIdx.x * blockDim.x + threadIdx.x;
    if (i < N_NODES) g_deg[i] = 0;
    if (i == 0) {
        g_total = 0;
        int z = 0;
#pragma unroll
        for (int k = 0; k < 16; k++) z |= ei32[2 * k + 1];
        g_is64 = (z == 0) ? 1 : 0;
    }
}

// In-degree count from the dst half of edge_index. 8 edges/thread.
__global__ void k_degree(const void* __restrict__ eiv) {
    int e = (blockIdx.x * blockDim.x + threadIdx.x) * 8;
    if (e >= N_EDGES) return;
    int d[8];
    if (g_is64) {
        const longlong2* p = (const longlong2*)((const long long*)eiv + N_EDGES + e);
#pragma unroll
        for (int q = 0; q < 4; q++) {
            longlong2 v = p[q];
            d[2*q]   = (int)v.x;
            d[2*q+1] = (int)v.y;
        }
    } else {
        const int4* p = (const int4*)((const int*)eiv + N_EDGES + e);
#pragma unroll
        for (int q = 0; q < 2; q++) {
            int4 v = p[q];
            d[4*q] = v.x; d[4*q+1] = v.y; d[4*q+2] = v.z; d[4*q+3] = v.w;
        }
    }
#pragma unroll
    for (int q = 0; q < 8; q++) atomicAdd(&g_deg[d[q]], 1);
}

// Allocate CSR buckets: warp shfl-scan of degrees + one atomicAdd per warp.
__global__ void k_offsets() {
    int i    = blockIdx.x * blockDim.x + threadIdx.x;
    int lane = threadIdx.x & 31;
    int deg  = (i < N_NODES) ? g_deg[i] : 0;

    int incl = deg;
#pragma unroll
    for (int o = 1; o < 32; o <<= 1) {
        int v = __shfl_up_sync(0xFFFFFFFFu, incl, o);
        if (lane >= o) incl += v;
    }
    int base = 0;
    if (lane == 31) base = atomicAdd(&g_total, incl);   // incl = warp total
    base = __shfl_sync(0xFFFFFFFFu, base, 31);

    if (i < N_NODES) {
        int off = base + incl - deg;
        g_rowptr[i] = off;
        g_cursor[i] = off;
        g_dinv[i]   = rsqrtf((float)(deg + 1));
    }
}

// ---------------------------------------------------------------------------
// FUSED: blocks [0, GB_FILL) scatter CSR; blocks [GB_FILL, ...) do gemm1.
// Independent work, disjoint bottlenecks (L2 atomics vs DRAM+FMA) -> overlap.
// gemm1 writes h1 PRE-SCALED by dinv[n].
__global__ void k_fill_gemm(const void* __restrict__ eiv,
                            const float* __restrict__ x,
                            const float* __restrict__ W1) {
    __shared__ float W1s[D_IN * D_HID];
    __shared__ float xs[16][D_IN];

    if (blockIdx.x < GB_FILL) {
        // ---- fillcsr part: 8 edges/thread ----
        int e = (blockIdx.x * blockDim.x + threadIdx.x) * 8;
        if (e >= N_EDGES) return;
        int s[8], d[8];
        if (g_is64) {
            const longlong2* ps = (const longlong2*)((const long long*)eiv + e);
            const longlong2* pd = (const longlong2*)((const long long*)eiv + N_EDGES + e);
#pragma unroll
            for (int q = 0; q < 4; q++) {
                longlong2 sv = ps[q], dv = pd[q];
                s[2*q]   = (int)sv.x;  s[2*q+1] = (int)sv.y;
                d[2*q]   = (int)dv.x;  d[2*q+1] = (int)dv.y;
            }
        } else {
            const int4* ps = (const int4*)((const int*)eiv + e);
            const int4* pd = (const int4*)((const int*)eiv + N_EDGES + e);
#pragma unroll
            for (int q = 0; q < 2; q++) {
                int4 sv = ps[q], dv = pd[q];
                s[4*q] = sv.x; s[4*q+1] = sv.y; s[4*q+2] = sv.z; s[4*q+3] = sv.w;
                d[4*q] = dv.x; d[4*q+1] = dv.y; d[4*q+2] = dv.z; d[4*q+3] = dv.w;
            }
        }
        int pos[8];
#pragma unroll
        for (int q = 0; q < 8; q++) pos[q] = atomicAdd(&g_cursor[d[q]], 1);
#pragma unroll
        for (int q = 0; q < 8; q++) g_csr[pos[q]] = s[q];
    } else {
        // ---- gemm1 part: 16 nodes/block, h1[n] = (x[n] @ W1) * dinv[n] ----
        int t  = threadIdx.x;
        int n0 = (blockIdx.x - GB_FILL) * 16;

        for (int idx = t; idx < D_IN * D_HID; idx += 256) W1s[idx] = W1[idx];
        const float4* x4 = (const float4*)x;
        for (int idx = t; idx < 16 * (D_IN / 4); idx += 256) {
            int ln = idx >> 5, q = idx & 31;
            int n  = n0 + ln;
            float4 v = (n < N_NODES) ? x4[n * (D_IN / 4) + q]
                                     : make_float4(0.f, 0.f, 0.f, 0.f);
            *(float4*)&xs[ln][q * 4] = v;
        }
        __syncthreads();

        int j = t & 15, ln = t >> 4;
        int n = n0 + ln;
        if (n < N_NODES) {
            float acc = 0.f;
#pragma unroll
            for (int k = 0; k < D_IN; k++)
                acc += xs[ln][k] * W1s[k * D_HID + j];
            g_h1[n * D_HID + j] = acc * g_dinv[n];
        }
    }
}

// Layer-1 aggregation + bias + relu + FUSED 16->2 projection.
// Half-warp per node, lane j = hidden feature. h1 pre-scaled: no dinv gather.
// Stores h2 PRE-SCALED by dinv[n].
__global__ void k_agg1(const float* __restrict__ b1, const float* __restrict__ W2) {
    int t = blockIdx.x * blockDim.x + threadIdx.x;
    int n = t >> 4;
    int j = t & 15;
    if (n >= N_NODES) return;

    float acc = g_h1[n * D_HID + j];           // self loop (pre-scaled)
    int p  = g_rowptr[n];
    int pe = p + g_deg[n];

    for (; p + 4 <= pe; p += 4) {
        int sa = g_csr[p + 0], sb = g_csr[p + 1];
        int sc = g_csr[p + 2], sd = g_csr[p + 3];
        float ha = g_h1[sa * D_HID + j], hb = g_h1[sb * D_HID + j];
        float hc = g_h1[sc * D_HID + j], hd = g_h1[sd * D_HID + j];
        acc += (ha + hb) + (hc + hd);
    }
    for (; p < pe; ++p) {
        int s = g_csr[p];
        acc += g_h1[s * D_HID + j];
    }

    float dn = g_dinv[n];
    float v  = fmaxf(acc * dn + b1[j], 0.f);

    // fused projection: reduce v*W2 across the 16 lanes of this node
    float z0 = v * W2[j * 2 + 0];
    float z1 = v * W2[j * 2 + 1];
#pragma unroll
    for (int o = 8; o; o >>= 1) {
        z0 += __shfl_xor_sync(0xFFFFFFFFu, z0, o, 16);
        z1 += __shfl_xor_sync(0xFFFFFFFFu, z1, o, 16);
    }
    if (j == 0) {
        g_h2[n * 2 + 0] = z0 * dn;             // pre-scale for layer 2
        g_h2[n * 2 + 1] = z1 * dn;
    }
}

// layer-2 aggregation + log_softmax: warp per node. h2 pre-scaled: no dinv gather.
__global__ void k_agg2(const float* __restrict__ b2, float* __restrict__ out) {
    int warp = (blockIdx.x * blockDim.x + threadIdx.x) >> 5;
    int lane = threadIdx.x & 31;
    if (warp >= N_NODES) return;
    int n  = warp;
    int p0 = g_rowptr[n];
    int p1 = p0 + g_deg[n];

    const float2* h2v = (const float2*)g_h2;
    float z0 = 0.f, z1 = 0.f;
    for (int p = p0 + lane; p < p1; p += 32) {
        int s   = g_csr[p];
        float2 h = h2v[s];
        z0 += h.x;
        z1 += h.y;
    }
#pragma unroll
    for (int o = 16; o; o >>= 1) {
        z0 += __shfl_xor_sync(0xFFFFFFFFu, z0, o);
        z1 += __shfl_xor_sync(0xFFFFFFFFu, z1, o);
    }
    if (lane == 0) {
        float dn = g_dinv[n];
        float2 hn = h2v[n];
        z0 = dn * (z0 + hn.x) + b2[0];
        z1 = dn * (z1 + hn.y) + b2[1];
        float m = fmaxf(z0, z1);
        float l = m + logf(expf(z0 - m) + expf(z1 - m));
        float2 r; r.x = z0 - l; r.y = z1 - l;
        *(float2*)(out + n * 2) = r;
    }
}

// ---------------------------------------------------------------------------
extern "C" void kernel_launch(void* const* d_in, const int* in_sizes, int n_in,
                              void* d_out, int out_size) {
    // Identify inputs by element count (all six are distinct).
    const float* x  = 0; const float* W1 = 0; const float* b1 = 0;
    const float* W2 = 0; const float* b2 = 0; const void*  ei = 0;
    for (int i = 0; i < n_in; i++) {
        switch (in_sizes[i]) {
            case N_NODES * D_IN: x  = (const float*)d_in[i]; break;  // 12,800,000
            case D_IN * D_HID:   W1 = (const float*)d_in[i]; break;  // 2048
            case D_HID:          b1 = (const float*)d_in[i]; break;  // 16
            case D_HID * D_OUT:  W2 = (const float*)d_in[i]; break;  // 32
            case D_OUT:          b2 = (const float*)d_in[i]; break;  // 2
            case 2 * N_EDGES:    ei = d_in[i];               break;  // 6,400,000
        }
    }
    float* out = (float*)d_out;

    k_init     <<<(N_NODES + 255) / 256, 256>>>((const int*)ei);
    k_degree   <<<(N_EDGES / 8 + 255) / 256, 256>>>(ei);
    k_offsets  <<<(N_NODES + 255) / 256, 256>>>();
    k_fill_gemm<<<GB_FILL + GB_GEMM, 256>>>(ei, x, W1);
    k_agg1     <<<(N_NODES * 16 + 255) / 256, 256>>>(b1, W2);
    k_agg2     <<<(N_NODES * 32 + 255) / 256, 256>>>(b2, out);
}